// round 6
// baseline (speedup 1.0000x reference)
#include <cuda_runtime.h>

#define HH 512
#define WW 512
#define NIMG 24            // 8 * 3 planes
#define KS 121
#define MEANR 60
#define NSTEP 61           // pair-steps = 122 taps (121 real + 1 zero)
#define PITCH 66           // floats per pair-row in shared (33 u64 -> conflict-free)

typedef unsigned long long u64;

__device__ float g_tmp[NIMG * HH * WW];

// packed fp32x2 fma: a.xy += b.xy * c.xy  (Blackwell FFMA2, PTX-only)
__device__ __forceinline__ void ffma2(u64& a, u64 b, u64 c) {
    asm("fma.rn.f32x2 %0, %1, %2, %0;" : "+l"(a) : "l"(b), "l"(c));
}
__device__ __forceinline__ float2 u2f(u64 v) {
    float2 r;
    asm("mov.b64 {%0, %1}, %2;" : "=f"(r.x), "=f"(r.y) : "l"(v));
    return r;
}

// Per-block weight prologue: duplicated-pair weights sw2[t] = (w[t], w[t]).
__device__ __forceinline__ void make_weights(const float* sigma, u64* sw2,
                                             float* sred, int tid) {
    float e = 0.0f;
    if (tid < 128) {
        float s = sigma[0] * 8.0f + 16.0f;
        float d = (float)(tid - MEANR);
        e = (tid < KS) ? expf(-(d * d) / (2.0f * s * s)) : 0.0f;
        sred[tid] = e;
    }
    __syncthreads();
    if (tid < 32) {
        float s4 = sred[tid] + sred[tid + 32] + sred[tid + 64] + sred[tid + 96];
        #pragma unroll
        for (int off = 16; off > 0; off >>= 1)
            s4 += __shfl_xor_sync(0xffffffffu, s4, off);
        if (tid == 0) sred[0] = s4;
    }
    __syncthreads();
    if (tid < 128) {
        float wv = e / sred[0];          // zero for tid >= KS
        float2 p; p.x = wv; p.y = wv;
        sw2[tid] = *(u64*)&p;
    }
}

// Core tap loop shared by both passes.
// base: u64 ptr to pair p0, lane slot; stride 33 u64 per pair (static offsets).
// Produces accE[0..7], accQ[0..7], accQ8; out[2m]=E[m].x+Q[m].y,
// out[2m+1]=E[m].y+Q[m+1].x (Q[8].x = accQ8.x).
__device__ __forceinline__ void tap_loop(const u64* __restrict__ base,
                                         const u64* __restrict__ sw2,
                                         u64* accE, u64* accQ, u64& accQ8) {
    u64 P[8];
    #pragma unroll
    for (int m = 0; m < 8; m++) { P[m] = base[m * 33]; accE[m] = 0ull; accQ[m] = 0ull; }
    accQ8 = 0ull;

    #pragma unroll
    for (int s = 0; s < NSTEP; s++) {
        ulonglong2 w2 = *(const ulonglong2*)(sw2 + 2 * s);   // LDS.128: (we, wo)
        #pragma unroll
        for (int m = 0; m < 8; m++) {
            ffma2(accE[m], w2.x, P[(s + m) & 7]);
            ffma2(accQ[m], w2.y, P[(s + m) & 7]);
        }
        u64 Pn = base[(s + 8) * 33];
        ffma2(accQ8, w2.y, Pn);
        P[s & 7] = Pn;
    }
}

// ---------------------------------------------------------------------------
// Horizontal pass: x -> g_tmp.  Block = 32 rows x 128 x-outputs.
// Warp w: x-columns [X0+16w, X0+16w+15], lanes = 32 rows.
// Shared sh[pair p][row r] (pitch 66 floats): pair p covers x = X0-64+2p.
// Warp pair base p0 = 8w+2.  All tap-loop LDS have static immediate offsets.
// ---------------------------------------------------------------------------
__global__ __launch_bounds__(256, 3) void hpass_kernel(const float* __restrict__ x,
                                                       const float* __restrict__ sigma) {
    __shared__ __align__(16) u64 sw2[128];
    __shared__ float sred[128];
    __shared__ float shf[128 * PITCH];     // 33792 B

    int tid = threadIdx.x;
    int X0 = blockIdx.x * 128;
    int r0 = blockIdx.y * 32;

    // load 256 x-inputs (clamped) x 32 rows; one row per iteration, coalesced
    {
        int xo = tid;
        int src = min(max(X0 - 64 + xo, 0), WW - 1);
        int sidx = (xo >> 1) * PITCH + (xo & 1);
        const float* xp = x + (long)r0 * WW + src;
        #pragma unroll 4
        for (int r = 0; r < 32; r++)
            shf[sidx + 2 * r] = xp[(long)r * WW];
    }
    make_weights(sigma, sw2, sred, tid);
    __syncthreads();

    int w = tid >> 5;
    int l = tid & 31;
    const u64* base = (const u64*)shf + (8 * w + 2) * 33 + l;

    u64 accE[8], accQ[8], accQ8;
    tap_loop(base, sw2, accE, accQ, accQ8);

    float2* orow = (float2*)(g_tmp + (long)(r0 + l) * WW + X0 + 16 * w);
    #pragma unroll
    for (int m = 0; m < 8; m++) {
        float2 E = u2f(accE[m]);
        float2 Q = u2f(accQ[m]);
        float qn = (m < 7) ? u2f(accQ[m + 1]).x : u2f(accQ8).x;
        orow[m] = make_float2(E.x + Q.y, E.y + qn);
    }
}

// ---------------------------------------------------------------------------
// Vertical pass: g_tmp -> out.  Block = 32 cols x 128 y-outputs.
// Warp w: y-rows [Y0+16w, Y0+16w+15], lanes = 32 cols.
// Shared sh[ypair p][col c] (pitch 66): pair p covers y = Y0-64+2p (clamped).
// ---------------------------------------------------------------------------
__global__ __launch_bounds__(256, 3) void vpass_kernel(float* __restrict__ out,
                                                       const float* __restrict__ sigma) {
    __shared__ __align__(16) u64 sw2[128];
    __shared__ float sred[128];
    __shared__ float shf[128 * PITCH];

    int tid = threadIdx.x;
    int img  = blockIdx.z;
    int col0 = blockIdx.x * 32;
    int Y0   = blockIdx.y * 128;
    const float* tp = g_tmp + (long)img * HH * WW + col0;

    // load 256 y-rows (clamped) x 32 cols; 8 rows per iteration, coalesced
    {
        int cc = tid & 31;
        int wy = tid >> 5;
        #pragma unroll 4
        for (int k = 0; k < 32; k++) {
            int yy = k * 8 + wy;
            int sy = min(max(Y0 - 64 + yy, 0), HH - 1);
            shf[(yy >> 1) * PITCH + 2 * cc + (yy & 1)] = tp[(long)sy * WW + cc];
        }
    }
    make_weights(sigma, sw2, sred, tid);
    __syncthreads();

    int w = tid >> 5;
    int c = tid & 31;
    const u64* base = (const u64*)shf + (8 * w + 2) * 33 + c;

    u64 accE[8], accQ[8], accQ8;
    tap_loop(base, sw2, accE, accQ, accQ8);

    float* op = out + (long)img * HH * WW + (long)(Y0 + 16 * w) * WW + col0 + c;
    #pragma unroll
    for (int m = 0; m < 8; m++) {
        float2 E = u2f(accE[m]);
        float2 Q = u2f(accQ[m]);
        float qn = (m < 7) ? u2f(accQ[m + 1]).x : u2f(accQ8).x;
        op[(long)(2 * m)     * WW] = E.x + Q.y;
        op[(long)(2 * m + 1) * WW] = E.y + qn;
    }
}

// ---------------------------------------------------------------------------
extern "C" void kernel_launch(void* const* d_in, const int* in_sizes, int n_in,
                              void* d_out, int out_size) {
    const float* x     = (const float*)d_in[0];
    const float* sigma = (const float*)d_in[1];
    float* out = (float*)d_out;

    dim3 hgrid(WW / 128, (NIMG * HH) / 32);      // 4 x 384 = 1536
    hpass_kernel<<<hgrid, 256>>>(x, sigma);

    dim3 vgrid(WW / 32, HH / 128, NIMG);         // 16 x 4 x 24 = 1536
    vpass_kernel<<<vgrid, 256>>>(out, sigma);
}